// round 4
// baseline (speedup 1.0000x reference)
#include <cuda_runtime.h>

#define Bv 128
#define Tv 1024
#define Nv 64

// Per-batch loss scratch (no cudaMalloc allowed).
__device__ float g_loss[Bv];

__global__ __launch_bounds__(64) void crf_kernel(
    const float* __restrict__ pot, const int* __restrict__ tags,
    const int* __restrict__ seqlen, const float* __restrict__ K,
    const float* __restrict__ w) {
  const int b = blockIdx.x;
  const int j = threadIdx.x;           // state index 0..63
  const int wid = j >> 5, lane = j & 31;
  const int L = seqlen[b];

  __shared__ float Ksh[Nv * 65];                 // padded: conflict-free column reads
  __shared__ __align__(16) float eabuf[2][Nv];   // ping-pong exp(alpha - A)
  __shared__ float redm[2][2];                   // ping-pong cross-warp max
  __shared__ float redx[2];                      // misc cross-warp reduce

  const float* potb = pot + (long)b * Tv * Nv;
  const int* tagb = tags + b * Tv;

  // Stage K into padded smem (coalesced gmem reads).
  for (int i = 0; i < Nv; i++) Ksh[i * 65 + j] = K[i * Nv + j];
  __syncthreads();

  // Thread j holds exp(K[i][j]) for all i in registers (one-time cost).
  float eKr[Nv];
#pragma unroll
  for (int i = 0; i < Nv; i++) eKr[i] = __expf(Ksh[i * 65 + j]);

  // ---- sequence score (unary + binary), strided gather pre-pass ----
  float sc = 0.f;
  for (int t = j; t < L; t += Nv) {
    int tg = tagb[t];
    sc += potb[t * Nv + tg];
    if (t >= 1) sc += Ksh[tagb[t - 1] * 65 + tg];
  }
#pragma unroll
  for (int o = 16; o > 0; o >>= 1) sc += __shfl_xor_sync(0xffffffffu, sc, o);
  if (lane == 0) redx[wid] = sc;

  // ---- scan init (t = 0) ----
  float aj = potb[j];                              // alpha0_j
  float potn = (L > 1) ? potb[Nv + j] : 0.f;       // prefetch pot[1]
  float m = aj;
#pragma unroll
  for (int o = 16; o > 0; o >>= 1) m = fmaxf(m, __shfl_xor_sync(0xffffffffu, m, o));
  if (lane == 0) redm[1][wid] = m;
  __syncthreads();
  float sscore = redx[0] + redx[1];
  float A_cur = fmaxf(redm[1][0], redm[1][1]);     // exact max(alpha0)
  eabuf[1][j] = __expf(aj - A_cur);
  __syncthreads();

  // ---- main scan: one __syncthreads per step, lagged-max rescale ----
  for (int t = 1; t < L; t++) {
    const int rb = t & 1;
    const int wb = rb ^ 1;
    float potc = potn;
    if (t + 1 < L) potn = potb[(t + 1) * Nv + j];  // prefetch next pot row
    float Anext = fmaxf(redm[rb][0], redm[rb][1]); // max(alpha_{t-1}), shadow-computed

    // s_j = sum_i exp(alpha_{t-1,i} - A_cur) * exp(K_ij); 8 independent acc chains
    const float4* e4 = (const float4*)eabuf[rb];
    float a0=0,a1=0,a2=0,a3=0,a4=0,a5=0,a6=0,a7=0;
#pragma unroll
    for (int q = 0; q < 8; q++) {
      float4 v0 = e4[2*q];
      float4 v1 = e4[2*q+1];
      a0 = fmaf(v0.x, eKr[8*q+0], a0);
      a1 = fmaf(v0.y, eKr[8*q+1], a1);
      a2 = fmaf(v0.z, eKr[8*q+2], a2);
      a3 = fmaf(v0.w, eKr[8*q+3], a3);
      a4 = fmaf(v1.x, eKr[8*q+4], a4);
      a5 = fmaf(v1.y, eKr[8*q+5], a5);
      a6 = fmaf(v1.z, eKr[8*q+6], a6);
      a7 = fmaf(v1.w, eKr[8*q+7], a7);
    }
    float s = ((a0 + a1) + (a2 + a3)) + ((a4 + a5) + (a6 + a7));

    aj = A_cur + __logf(s) + potc;                 // alpha_t,j
    float e = __expf(aj - Anext);                  // rescale with 1-step-lagged max
    eabuf[wb][j] = e;

    // shadow: cross-warp max of alpha_t for use at step t+1
    float mm = aj;
#pragma unroll
    for (int o = 16; o > 0; o >>= 1) mm = fmaxf(mm, __shfl_xor_sync(0xffffffffu, mm, o));
    if (lane == 0) redm[wb][wid] = mm;

    A_cur = Anext;
    __syncthreads();
  }

  // ---- final logsumexp(alpha_{L-1}) exactly ----
  float mf = aj;
#pragma unroll
  for (int o = 16; o > 0; o >>= 1) mf = fmaxf(mf, __shfl_xor_sync(0xffffffffu, mf, o));
  if (lane == 0) redm[0][wid] = mf;
  __syncthreads();
  float Mx = fmaxf(redm[0][0], redm[0][1]);
  float se = __expf(aj - Mx);
#pragma unroll
  for (int o = 16; o > 0; o >>= 1) se += __shfl_xor_sync(0xffffffffu, se, o);
  if (lane == 0) redx[wid] = se;
  __syncthreads();
  if (j == 0) {
    float logZ = Mx + __logf(redx[0] + redx[1]);
    g_loss[b] = -(sscore - logZ) * w[b];
  }
}

__global__ __launch_bounds__(128) void reduce_kernel(float* __restrict__ out) {
  int j = threadIdx.x;  // 128 threads, one per batch
  float v = g_loss[j];
  __shared__ float sh[4];
#pragma unroll
  for (int o = 16; o > 0; o >>= 1) v += __shfl_xor_sync(0xffffffffu, v, o);
  if ((j & 31) == 0) sh[j >> 5] = v;
  __syncthreads();
  if (j == 0) out[0] = (sh[0] + sh[1] + sh[2] + sh[3]) * (1.0f / Bv);
}

extern "C" void kernel_launch(void* const* d_in, const int* in_sizes, int n_in,
                              void* d_out, int out_size) {
  const float* pot    = (const float*)d_in[0];  // potentials [128,1024,64] f32
  const int*   tags   = (const int*)  d_in[1];  // tags [128,1024] i32
  const int*   seqlen = (const int*)  d_in[2];  // sequence_length [128] i32
  const float* K      = (const float*)d_in[3];  // chain_kernel [64,64] f32
  const float* w      = (const float*)d_in[4];  // sample_weight [128] f32
  crf_kernel<<<Bv, Nv>>>(pot, tags, seqlen, K, w);
  reduce_kernel<<<1, Bv>>>((float*)d_out);
}

// round 6
// speedup vs baseline: 2.0927x; 2.0927x over previous
#include <cuda_runtime.h>

#define Bv 128
#define Tv 1024
#define Nv 64
#define U 8

// Scratch (no cudaMalloc allowed). g_ctr wraps back to 0 every full run -> graph-safe.
__device__ float g_loss[Bv];
__device__ unsigned g_ctr = 0;

#define FMA_X2(d, a, b, c) \
  asm("fma.rn.f32x2 %0, %1, %2, %3;" : "=l"(d) : "l"(a), "l"(b), "l"(c))
#define ADD_X2(d, a, b) \
  asm("add.rn.f32x2 %0, %1, %2;" : "=l"(d) : "l"(a), "l"(b))

__global__ __launch_bounds__(64) void crf_kernel(
    const float* __restrict__ pot, const int* __restrict__ tags,
    const int* __restrict__ seqlen, const float* __restrict__ K,
    const float* __restrict__ w, float* __restrict__ out) {
  const int b = blockIdx.x;
  const int j = threadIdx.x;           // state 0..63
  const int wid = j >> 5, lane = j & 31;
  const int L = seqlen[b];

  __shared__ float Ksh[Nv * 65];                 // padded for column reads
  __shared__ __align__(16) float eabuf[2][Nv];   // ping-pong exp(alpha - C)
  __shared__ float sbase[2];                     // ping-pong alpha[t][0] (rescale base)
  __shared__ float redx[2], redm2[2];
  __shared__ int slast;

  const float* potb = pot + (long)b * Tv * Nv;
  const int* tagb = tags + b * Tv;

  for (int i = 0; i < Nv; i++) Ksh[i * 65 + j] = K[i * Nv + j];
  __syncthreads();

  // ---- sequence score: batched loads for high MLP (all indices in-bounds by
  // construction: t = j + 64u <= 1023, tags in [0,64)) ----
  int tg[16], tp[16];
#pragma unroll
  for (int u = 0; u < 16; u++) {
    int t = j + 64 * u;
    tg[u] = tagb[t];
    tp[u] = tagb[t > 0 ? t - 1 : 0];
  }
  float pv[16];
#pragma unroll
  for (int u = 0; u < 16; u++) pv[u] = potb[(j + 64 * u) * Nv + tg[u]];
  float sc = 0.f;
#pragma unroll
  for (int u = 0; u < 16; u++) {
    int t = j + 64 * u;
    if (t < L) {
      sc += pv[u];
      if (t >= 1) sc += Ksh[tp[u] * 65 + tg[u]];
    }
  }
#pragma unroll
  for (int o = 16; o > 0; o >>= 1) sc += __shfl_xor_sync(0xffffffffu, sc, o);
  if (lane == 0) redx[wid] = sc;

  // ---- exp(K) column j, packed as f32x2 pairs along i ----
  unsigned long long eK2[32];
#pragma unroll
  for (int p = 0; p < 32; p++) {
    float e0 = __expf(Ksh[(2 * p) * 65 + j]);
    float e1 = __expf(Ksh[(2 * p + 1) * 65 + j]);
    asm("mov.b64 %0, {%1, %2};" : "=l"(eK2[p]) : "f"(e0), "f"(e1));
  }

  // ---- scan init (t = 0); base = alpha[0][0] ----
  float aj = potb[j];
  float pc[U], pn[U];
#pragma unroll
  for (int u = 0; u < U; u++) {          // pot rows for t = 1..U (clamped)
    int t = 1 + u; if (t > L - 1) t = L - 1;
    pc[u] = potb[t * Nv + j];
  }
  if (j == 0) sbase[1] = aj;
  __syncthreads();
  float sscore = redx[0] + redx[1];
  float A_cur = sbase[1];                // C_0 = alpha[0][0]
  eabuf[1][j] = __expf(aj - A_cur);
  __syncthreads();

  // ---- main scan: chunked U-deep pot prefetch, one bar per step ----
  for (int tb = 1; tb < L; tb += U) {
    const int nb = tb + U;
#pragma unroll
    for (int u = 0; u < U; u++) {        // prefetch next chunk (clamped, branch-free)
      int t = nb + u; if (t > L - 1) t = L - 1;
      pn[u] = potb[t * Nv + j];
    }
#pragma unroll
    for (int u = 0; u < U; u++) {
      const int tt = tb + u;
      if (tt >= L) break;                // uniform across block
      const int rb = tt & 1, wb = rb ^ 1;
      float Cnew = sbase[rb];            // alpha[t-1][0], stored last step
      const ulonglong2* e2 = (const ulonglong2*)eabuf[rb];
      unsigned long long acc[4] = {0ull, 0ull, 0ull, 0ull};
#pragma unroll
      for (int q = 0; q < 16; q++) {     // 32 packed FMAs = 64 scalar MACs
        ulonglong2 v = e2[q];
        FMA_X2(acc[(2 * q) & 3], v.x, eK2[2 * q], acc[(2 * q) & 3]);
        FMA_X2(acc[(2 * q + 1) & 3], v.y, eK2[2 * q + 1], acc[(2 * q + 1) & 3]);
      }
      unsigned long long s01, s23, sA;
      ADD_X2(s01, acc[0], acc[1]);
      ADD_X2(s23, acc[2], acc[3]);
      ADD_X2(sA, s01, s23);
      float slo, shi;
      asm("mov.b64 {%0, %1}, %2;" : "=f"(slo), "=f"(shi) : "l"(sA));
      float s = slo + shi;

      float l2 = __log2f(s);
      float cpre = A_cur + pc[u];                        // C_{t-1} + pot_t (off-chain)
      float ex = fmaf(cpre - Cnew, 1.4426950408889634f, l2);
      float e;
      asm("ex2.approx.f32 %0, %1;" : "=f"(e) : "f"(ex)); // exp(alpha_t - C_t)
      eabuf[wb][j] = e;
      aj = fmaf(l2, 0.6931471805599453f, cpre);          // alpha_t (parallel path)
      if (j == 0) sbase[wb] = aj;
      A_cur = Cnew;
      __syncthreads();
    }
#pragma unroll
    for (int u = 0; u < U; u++) pc[u] = pn[u];
  }

  // ---- exact final logsumexp(alpha_{L-1}) ----
  float mf = aj;
#pragma unroll
  for (int o = 16; o > 0; o >>= 1) mf = fmaxf(mf, __shfl_xor_sync(0xffffffffu, mf, o));
  if (lane == 0) redm2[wid] = mf;
  __syncthreads();
  float Mx = fmaxf(redm2[0], redm2[1]);
  float se = __expf(aj - Mx);
#pragma unroll
  for (int o = 16; o > 0; o >>= 1) se += __shfl_xor_sync(0xffffffffu, se, o);
  if (lane == 0) redx[wid] = se;
  __syncthreads();

  // ---- per-batch loss + fused last-block-done mean ----
  if (j == 0) {
    float logZ = Mx + __logf(redx[0] + redx[1]);
    g_loss[b] = -(sscore - logZ) * w[b];
    __threadfence();
    unsigned old = atomicInc(&g_ctr, Bv - 1);  // wraps to 0 each full run
    slast = (old == (unsigned)(Bv - 1)) ? 1 : 0;
  }
  __syncthreads();
  if (slast) {
    float v = __ldcg(&g_loss[j]) + __ldcg(&g_loss[j + 64]);
#pragma unroll
    for (int o = 16; o > 0; o >>= 1) v += __shfl_xor_sync(0xffffffffu, v, o);
    if (lane == 0) redx[wid] = v;
    __syncthreads();
    if (j == 0) out[0] = (redx[0] + redx[1]) * (1.0f / (float)Bv);
  }
}

extern "C" void kernel_launch(void* const* d_in, const int* in_sizes, int n_in,
                              void* d_out, int out_size) {
  const float* pot    = (const float*)d_in[0];  // [128,1024,64] f32
  const int*   tags   = (const int*)  d_in[1];  // [128,1024] i32
  const int*   seqlen = (const int*)  d_in[2];  // [128] i32
  const float* K      = (const float*)d_in[3];  // [64,64] f32
  const float* w      = (const float*)d_in[4];  // [128] f32
  crf_kernel<<<Bv, Nv>>>(pot, tags, seqlen, K, w, (float*)d_out);
}